// round 14
// baseline (speedup 1.0000x reference)
#include <cuda_runtime.h>
#include <cuda_fp16.h>
#include <cstdint>

#define MAX_NODES 50048
#define IN_DIM    128
#define OUT_DIM   64
#define LEAKY     0.01f
#define CAP       128           // slots per destination node (max degree ~35)

typedef unsigned long long ull;

// ---------------- scratch (device globals; zero-initialized at load) -------
__device__ uint2 g_zu[MAX_NODES * 16];        // projected features fp16; row=128B
__device__ float g_azs[MAX_NODES];            // z . a[:64]  (fp32 precision)
__device__ float g_azd[MAX_NODES];            // z . a[64:]
__device__ int   g_cnt[MAX_NODES];            // per-dst cursor/degree (re-zeroed by scatter)
__device__ int2  g_sw[MAX_NODES * CAP];       // slotted CSR: (src*8, exp(e) bits)

// ---------------- packed f32x2 helpers --------------------------------------
__device__ __forceinline__ ull pack2(float lo, float hi) {
    ull r;
    asm("mov.b64 %0, {%1, %2};" : "=l"(r) : "f"(lo), "f"(hi));
    return r;
}
__device__ __forceinline__ void ffma2(ull& d, ull a, ull b) {
    asm("fma.rn.f32x2 %0, %1, %2, %0;" : "+l"(d) : "l"(a), "l"(b));
}
__device__ __forceinline__ float2 unpack2(ull v) {
    float lo, hi;
    asm("mov.b64 {%0, %1}, %2;" : "=f"(lo), "=f"(hi) : "l"(v));
    return make_float2(lo, hi);
}

// ---------------- kernel 1: tiled projection ---------------------------------
// 256 threads cover 64 nodes. Thread owns 4 nodes x 4 output cols (2 pairs).
// ~50 regs -> 5 blocks/SM (40 warps); grid 782 -> no wave quantization.
__global__ void __launch_bounds__(256)
proj_kernel(const float* __restrict__ feat,
            const float* __restrict__ W,
            const float* __restrict__ a,
            int n_nodes) {
    int tid = threadIdx.x;

    __shared__ ull   Ws2[IN_DIM * 32];   // [k][pair], 32 KB
    __shared__ float as[2 * OUT_DIM];

    const float4* W4 = reinterpret_cast<const float4*>(W);
    for (int i = tid; i < IN_DIM * OUT_DIM / 4; i += 256) {
        float4 w = W4[i];
        Ws2[2 * i]     = pack2(w.x, w.y);
        Ws2[2 * i + 1] = pack2(w.z, w.w);
    }
    if (tid < 2 * OUT_DIM) as[tid] = a[tid];
    __syncthreads();

    int jg = tid & 15;                      // pair group: pairs jg*2, jg*2+1
    int n0 = blockIdx.x * 64 + (tid >> 4) * 4;
    // clamp so n0..n0+3 are all valid; duplicate (identical) work at the tail
    if (n0 > n_nodes - 4) n0 = n_nodes - 4;

    ull acc[4][2];
#pragma unroll
    for (int i = 0; i < 4; i++) { acc[i][0] = 0ull; acc[i][1] = 0ull; }

    const float4* fbase = reinterpret_cast<const float4*>(feat + (size_t)n0 * IN_DIM);

    for (int k4 = 0; k4 < IN_DIM / 4; k4++) {
        ull wp[8];
#pragma unroll
        for (int ks = 0; ks < 4; ks++) {
            int k = k4 * 4 + ks;
            wp[2 * ks]     = Ws2[k * 32 + jg * 2];
            wp[2 * ks + 1] = Ws2[k * 32 + jg * 2 + 1];
        }
#pragma unroll
        for (int i = 0; i < 4; i++) {
            float4 f = fbase[i * (IN_DIM / 4) + k4];   // transient
            ull fx = pack2(f.x, f.x);
            ffma2(acc[i][0], fx, wp[0]);
            ffma2(acc[i][1], fx, wp[1]);
            ull fy = pack2(f.y, f.y);
            ffma2(acc[i][0], fy, wp[2]);
            ffma2(acc[i][1], fy, wp[3]);
            ull fz = pack2(f.z, f.z);
            ffma2(acc[i][0], fz, wp[4]);
            ffma2(acc[i][1], fz, wp[5]);
            ull fw = pack2(f.w, f.w);
            ffma2(acc[i][0], fw, wp[6]);
            ffma2(acc[i][1], fw, wp[7]);
        }
    }

    // az partials per node, reduced across the 16 jg lanes
#pragma unroll
    for (int i = 0; i < 4; i++) {
        float2 v0 = unpack2(acc[i][0]);
        float2 v1 = unpack2(acc[i][1]);
        int c0 = jg * 4;
        float s0 = v0.x * as[c0]     + v0.y * as[c0 + 1]
                 + v1.x * as[c0 + 2] + v1.y * as[c0 + 3];
        float s1 = v0.x * as[OUT_DIM + c0]     + v0.y * as[OUT_DIM + c0 + 1]
                 + v1.x * as[OUT_DIM + c0 + 2] + v1.y * as[OUT_DIM + c0 + 3];
        s0 += __shfl_xor_sync(0xffffffffu, s0, 1);
        s0 += __shfl_xor_sync(0xffffffffu, s0, 2);
        s0 += __shfl_xor_sync(0xffffffffu, s0, 4);
        s0 += __shfl_xor_sync(0xffffffffu, s0, 8);
        s1 += __shfl_xor_sync(0xffffffffu, s1, 1);
        s1 += __shfl_xor_sync(0xffffffffu, s1, 2);
        s1 += __shfl_xor_sync(0xffffffffu, s1, 4);
        s1 += __shfl_xor_sync(0xffffffffu, s1, 8);
        if (jg == 0) {
            g_azs[n0 + i] = s0;
            g_azd[n0 + i] = s1;
        }
    }

    // z stores: fp16; 2 half2 = 8B = 1 uint2 per node per thread
#pragma unroll
    for (int i = 0; i < 4; i++) {
        __half2 h0 = __float22half2_rn(unpack2(acc[i][0]));
        __half2 h1 = __float22half2_rn(unpack2(acc[i][1]));
        uint2 v;
        v.x = *reinterpret_cast<unsigned*>(&h0);
        v.y = *reinterpret_cast<unsigned*>(&h1);
        g_zu[(size_t)(n0 + i) * 16 + jg] = v;
    }
}

// ---------------- kernel 2: edge weights + slotted CSR fill ------------------
// No scan needed: slot = atomicAdd(cursor). 4 edges/thread via int4 loads.
__global__ void __launch_bounds__(256)
fill_kernel(const int* __restrict__ src,
            const int* __restrict__ dst,
            int n_edges) {
    int t = blockIdx.x * 256 + threadIdx.x;
    int e0 = t * 4;
    if (e0 >= n_edges) return;

    if (e0 + 3 < n_edges) {
        int4 s4 = *reinterpret_cast<const int4*>(src + e0);
        int4 d4 = *reinterpret_cast<const int4*>(dst + e0);
        float ea = g_azs[s4.x] + g_azd[d4.x];
        float eb = g_azs[s4.y] + g_azd[d4.y];
        float ec = g_azs[s4.z] + g_azd[d4.z];
        float ed = g_azs[s4.w] + g_azd[d4.w];
        ea = (ea > 0.f) ? ea : LEAKY * ea;
        eb = (eb > 0.f) ? eb : LEAKY * eb;
        ec = (ec > 0.f) ? ec : LEAKY * ec;
        ed = (ed > 0.f) ? ed : LEAKY * ed;
        float wa = __expf(ea), wb = __expf(eb);
        float wc = __expf(ec), wd = __expf(ed);
        int pa = atomicAdd(&g_cnt[d4.x], 1);
        int pb = atomicAdd(&g_cnt[d4.y], 1);
        int pc = atomicAdd(&g_cnt[d4.z], 1);
        int pd = atomicAdd(&g_cnt[d4.w], 1);
        if (pa < CAP) g_sw[(size_t)d4.x * CAP + pa] = make_int2(s4.x << 3, __float_as_int(wa));
        if (pb < CAP) g_sw[(size_t)d4.y * CAP + pb] = make_int2(s4.y << 3, __float_as_int(wb));
        if (pc < CAP) g_sw[(size_t)d4.z * CAP + pc] = make_int2(s4.z << 3, __float_as_int(wc));
        if (pd < CAP) g_sw[(size_t)d4.w * CAP + pd] = make_int2(s4.w << 3, __float_as_int(wd));
    } else {
        for (int e = e0; e < n_edges; e++) {
            int s = src[e], d = dst[e];
            float ee = g_azs[s] + g_azd[d];
            ee = (ee > 0.f) ? ee : LEAKY * ee;
            float w = __expf(ee);
            int pos = atomicAdd(&g_cnt[d], 1);
            if (pos < CAP) g_sw[(size_t)d * CAP + pos] = make_int2(s << 3, __float_as_int(w));
        }
    }
}

// ---------------- kernel 3: four destination nodes per warp ------------------
// Quarter-warp (8 lanes) owns one node; lane owns uint4 = 8 fp16 cols (16B);
// full 128B row in one LDG.128 per edge. SBATCH=4; fp32 accumulation.
#define SBATCH 4
__global__ void __launch_bounds__(256)
scatter_kernel(float* __restrict__ h, int n_nodes) {
    int warp_id = (blockIdx.x * 256 + threadIdx.x) >> 5;
    int lane = threadIdx.x & 31;
    int qw = lane >> 3;          // quarter-warp id: 0..3
    int ln = lane & 7;           // uint4 index within row

    int node = warp_id * 4 + qw;
    bool valid = node < n_nodes;

    int cnt = valid ? g_cnt[node] : 0;
    cnt = (cnt < CAP) ? cnt : CAP;          // memory-safety guard (never binds)

    const uint4* zrow = reinterpret_cast<const uint4*>(g_zu) + ln;
    const int2* sw = g_sw + (size_t)(valid ? node : 0) * CAP;

    ull acc0 = 0ull, acc1 = 0ull, acc2 = 0ull, acc3 = 0ull;
    float wsum = 0.f;

    for (int base = 0; base < cnt; base += SBATCH) {
        int m = cnt - base;
        int2 e[SBATCH];
#pragma unroll
        for (int j = 0; j < SBATCH; j++)
            e[j] = (j < m) ? __ldg(sw + base + j) : make_int2(0, 0);
        uint4 zv[SBATCH];
#pragma unroll
        for (int j = 0; j < SBATCH; j++)
            zv[j] = zrow[e[j].x];        // e.x = src*8 (uint4 row offset)
#pragma unroll
        for (int j = 0; j < SBATCH; j++) {
            float w = __int_as_float(e[j].y);
            wsum += w;
            ull wk = pack2(w, w);
            float2 z0 = __half22float2(*reinterpret_cast<__half2*>(&zv[j].x));
            float2 z1 = __half22float2(*reinterpret_cast<__half2*>(&zv[j].y));
            float2 z2 = __half22float2(*reinterpret_cast<__half2*>(&zv[j].z));
            float2 z3 = __half22float2(*reinterpret_cast<__half2*>(&zv[j].w));
            ffma2(acc0, wk, pack2(z0.x, z0.y));
            ffma2(acc1, wk, pack2(z1.x, z1.y));
            ffma2(acc2, wk, pack2(z2.x, z2.y));
            ffma2(acc3, wk, pack2(z3.x, z3.y));
        }
    }

    float inv = (cnt > 0) ? 1.f / wsum : 0.f;
    if (valid) {
        float2 a = unpack2(acc0), b = unpack2(acc1);
        float2 c = unpack2(acc2), d = unpack2(acc3);
        float4* out = reinterpret_cast<float4*>(h + (size_t)node * OUT_DIM);
        out[ln * 2]     = make_float4(a.x * inv, a.y * inv, b.x * inv, b.y * inv);
        out[ln * 2 + 1] = make_float4(c.x * inv, c.y * inv, d.x * inv, d.y * inv);
        if (ln == 0) g_cnt[node] = 0;    // restore invariant for next replay
    }
}

// ---------------- launch ------------------------------------------------------
extern "C" void kernel_launch(void* const* d_in, const int* in_sizes, int n_in,
                              void* d_out, int out_size) {
    const float* feat = (const float*)d_in[0];
    const int*   src  = (const int*)  d_in[1];
    const int*   dst  = (const int*)  d_in[2];
    const float* W    = (const float*)d_in[3];
    const float* a    = (const float*)d_in[4];
    float* h = (float*)d_out;

    int n_nodes = in_sizes[0] / IN_DIM;
    int n_edges = in_sizes[1];

    proj_kernel<<<(n_nodes + 63) / 64, 256>>>(feat, W, a, n_nodes);

    fill_kernel<<<(n_edges / 4 + 255) / 256, 256>>>(src, dst, n_edges);

    {
        int warps = (n_nodes + 3) / 4;
        int blocks = (warps + 7) / 8;    // 8 warps/block
        scatter_kernel<<<blocks, 256>>>(h, n_nodes);
    }
}

// round 15
// speedup vs baseline: 1.2177x; 1.2177x over previous
#include <cuda_runtime.h>
#include <cuda_fp16.h>
#include <cstdint>

#define MAX_NODES 50048
#define IN_DIM    128
#define OUT_DIM   64
#define LEAKY     0.01f
#define CAP       128           // slots per destination node (max degree ~35)

typedef unsigned long long ull;

// ---------------- scratch (device globals; zero-initialized at load) -------
__device__ uint2 g_zu[MAX_NODES * 16];        // projected features fp16; row=128B
__device__ float g_azs[MAX_NODES];            // z . a[:64]  (fp32 precision)
__device__ float g_azd[MAX_NODES];            // z . a[64:]
__device__ int   g_cnt[MAX_NODES];            // per-dst cursor/degree (re-zeroed by scatter)
__device__ int2  g_sw[MAX_NODES * CAP];       // slotted CSR: (src*8, exp(e) bits)

// ---------------- packed f32x2 helpers --------------------------------------
__device__ __forceinline__ ull pack2(float lo, float hi) {
    ull r;
    asm("mov.b64 %0, {%1, %2};" : "=l"(r) : "f"(lo), "f"(hi));
    return r;
}
__device__ __forceinline__ void ffma2(ull& d, ull a, ull b) {
    asm("fma.rn.f32x2 %0, %1, %2, %0;" : "+l"(d) : "l"(a), "l"(b));
}
__device__ __forceinline__ float2 unpack2(ull v) {
    float lo, hi;
    asm("mov.b64 {%0, %1}, %2;" : "=f"(lo), "=f"(hi) : "l"(v));
    return make_float2(lo, hi);
}

// ---------------- kernel 1: tiled projection ---------------------------------
// 128 threads cover 64 nodes. Thread owns 8 nodes x 4 output cols (2 pairs)
// -- the R13 LDS-efficient tile. k4 loop unrolled x2 so ptxas batches the
// next iteration's f LDGs behind the current FFMA2 stream (MLP 8 -> 16).
__global__ void __launch_bounds__(128)
proj_kernel(const float* __restrict__ feat,
            const float* __restrict__ W,
            const float* __restrict__ a,
            int n_nodes) {
    int tid = threadIdx.x;

    __shared__ ull   Ws2[IN_DIM * 32];   // [k][pair], 32 KB
    __shared__ float as[2 * OUT_DIM];

    const float4* W4 = reinterpret_cast<const float4*>(W);
    for (int i = tid; i < IN_DIM * OUT_DIM / 4; i += 128) {
        float4 w = W4[i];
        Ws2[2 * i]     = pack2(w.x, w.y);
        Ws2[2 * i + 1] = pack2(w.z, w.w);
    }
    if (tid < 2 * OUT_DIM) as[tid] = a[tid];
    __syncthreads();

    int jg = tid & 15;                      // pair group: pairs jg*2, jg*2+1
    int n0 = blockIdx.x * 64 + (tid >> 4) * 8;
    // clamp so n0..n0+7 are all valid; duplicate (identical) work at the tail
    if (n0 > n_nodes - 8) n0 = n_nodes - 8;

    ull acc[8][2];
#pragma unroll
    for (int i = 0; i < 8; i++) { acc[i][0] = 0ull; acc[i][1] = 0ull; }

    const float4* fbase = reinterpret_cast<const float4*>(feat + (size_t)n0 * IN_DIM);

#pragma unroll 2
    for (int k4 = 0; k4 < IN_DIM / 4; k4++) {
        ull wp[8];
#pragma unroll
        for (int ks = 0; ks < 4; ks++) {
            int k = k4 * 4 + ks;
            wp[2 * ks]     = Ws2[k * 32 + jg * 2];
            wp[2 * ks + 1] = Ws2[k * 32 + jg * 2 + 1];
        }
#pragma unroll
        for (int i = 0; i < 8; i++) {
            float4 f = fbase[i * (IN_DIM / 4) + k4];   // transient
            ull fx = pack2(f.x, f.x);
            ffma2(acc[i][0], fx, wp[0]);
            ffma2(acc[i][1], fx, wp[1]);
            ull fy = pack2(f.y, f.y);
            ffma2(acc[i][0], fy, wp[2]);
            ffma2(acc[i][1], fy, wp[3]);
            ull fz = pack2(f.z, f.z);
            ffma2(acc[i][0], fz, wp[4]);
            ffma2(acc[i][1], fz, wp[5]);
            ull fw = pack2(f.w, f.w);
            ffma2(acc[i][0], fw, wp[6]);
            ffma2(acc[i][1], fw, wp[7]);
        }
    }

    // az partials per node, reduced across the 16 jg lanes
#pragma unroll
    for (int i = 0; i < 8; i++) {
        float2 v0 = unpack2(acc[i][0]);
        float2 v1 = unpack2(acc[i][1]);
        int c0 = jg * 4;
        float s0 = v0.x * as[c0]     + v0.y * as[c0 + 1]
                 + v1.x * as[c0 + 2] + v1.y * as[c0 + 3];
        float s1 = v0.x * as[OUT_DIM + c0]     + v0.y * as[OUT_DIM + c0 + 1]
                 + v1.x * as[OUT_DIM + c0 + 2] + v1.y * as[OUT_DIM + c0 + 3];
        s0 += __shfl_xor_sync(0xffffffffu, s0, 1);
        s0 += __shfl_xor_sync(0xffffffffu, s0, 2);
        s0 += __shfl_xor_sync(0xffffffffu, s0, 4);
        s0 += __shfl_xor_sync(0xffffffffu, s0, 8);
        s1 += __shfl_xor_sync(0xffffffffu, s1, 1);
        s1 += __shfl_xor_sync(0xffffffffu, s1, 2);
        s1 += __shfl_xor_sync(0xffffffffu, s1, 4);
        s1 += __shfl_xor_sync(0xffffffffu, s1, 8);
        if (jg == 0) {
            g_azs[n0 + i] = s0;
            g_azd[n0 + i] = s1;
        }
    }

    // z stores: fp16; 2 half2 = 8B = 1 uint2 per node per thread
#pragma unroll
    for (int i = 0; i < 8; i++) {
        __half2 h0 = __float22half2_rn(unpack2(acc[i][0]));
        __half2 h1 = __float22half2_rn(unpack2(acc[i][1]));
        uint2 v;
        v.x = *reinterpret_cast<unsigned*>(&h0);
        v.y = *reinterpret_cast<unsigned*>(&h1);
        g_zu[(size_t)(n0 + i) * 16 + jg] = v;
    }
}

// ---------------- kernel 2: edge weights + slotted CSR fill ------------------
// No scan needed: slot = atomicAdd(cursor). 4 edges/thread via int4 loads.
__global__ void __launch_bounds__(256)
fill_kernel(const int* __restrict__ src,
            const int* __restrict__ dst,
            int n_edges) {
    int t = blockIdx.x * 256 + threadIdx.x;
    int e0 = t * 4;
    if (e0 >= n_edges) return;

    if (e0 + 3 < n_edges) {
        int4 s4 = *reinterpret_cast<const int4*>(src + e0);
        int4 d4 = *reinterpret_cast<const int4*>(dst + e0);
        float ea = g_azs[s4.x] + g_azd[d4.x];
        float eb = g_azs[s4.y] + g_azd[d4.y];
        float ec = g_azs[s4.z] + g_azd[d4.z];
        float ed = g_azs[s4.w] + g_azd[d4.w];
        ea = (ea > 0.f) ? ea : LEAKY * ea;
        eb = (eb > 0.f) ? eb : LEAKY * eb;
        ec = (ec > 0.f) ? ec : LEAKY * ec;
        ed = (ed > 0.f) ? ed : LEAKY * ed;
        float wa = __expf(ea), wb = __expf(eb);
        float wc = __expf(ec), wd = __expf(ed);
        int pa = atomicAdd(&g_cnt[d4.x], 1);
        int pb = atomicAdd(&g_cnt[d4.y], 1);
        int pc = atomicAdd(&g_cnt[d4.z], 1);
        int pd = atomicAdd(&g_cnt[d4.w], 1);
        if (pa < CAP) g_sw[(size_t)d4.x * CAP + pa] = make_int2(s4.x << 3, __float_as_int(wa));
        if (pb < CAP) g_sw[(size_t)d4.y * CAP + pb] = make_int2(s4.y << 3, __float_as_int(wb));
        if (pc < CAP) g_sw[(size_t)d4.z * CAP + pc] = make_int2(s4.z << 3, __float_as_int(wc));
        if (pd < CAP) g_sw[(size_t)d4.w * CAP + pd] = make_int2(s4.w << 3, __float_as_int(wd));
    } else {
        for (int e = e0; e < n_edges; e++) {
            int s = src[e], d = dst[e];
            float ee = g_azs[s] + g_azd[d];
            ee = (ee > 0.f) ? ee : LEAKY * ee;
            float w = __expf(ee);
            int pos = atomicAdd(&g_cnt[d], 1);
            if (pos < CAP) g_sw[(size_t)d * CAP + pos] = make_int2(s << 3, __float_as_int(w));
        }
    }
}

// ---------------- kernel 3: four destination nodes per warp ------------------
// Quarter-warp (8 lanes) owns one node; lane owns uint4 = 8 fp16 cols (16B);
// full 128B row in one LDG.128 per edge. SBATCH=4; fp32 accumulation.
#define SBATCH 4
__global__ void __launch_bounds__(256)
scatter_kernel(float* __restrict__ h, int n_nodes) {
    int warp_id = (blockIdx.x * 256 + threadIdx.x) >> 5;
    int lane = threadIdx.x & 31;
    int qw = lane >> 3;          // quarter-warp id: 0..3
    int ln = lane & 7;           // uint4 index within row

    int node = warp_id * 4 + qw;
    bool valid = node < n_nodes;

    int cnt = valid ? g_cnt[node] : 0;
    cnt = (cnt < CAP) ? cnt : CAP;          // memory-safety guard (never binds)

    const uint4* zrow = reinterpret_cast<const uint4*>(g_zu) + ln;
    const int2* sw = g_sw + (size_t)(valid ? node : 0) * CAP;

    ull acc0 = 0ull, acc1 = 0ull, acc2 = 0ull, acc3 = 0ull;
    float wsum = 0.f;

    for (int base = 0; base < cnt; base += SBATCH) {
        int m = cnt - base;
        int2 e[SBATCH];
#pragma unroll
        for (int j = 0; j < SBATCH; j++)
            e[j] = (j < m) ? __ldg(sw + base + j) : make_int2(0, 0);
        uint4 zv[SBATCH];
#pragma unroll
        for (int j = 0; j < SBATCH; j++)
            zv[j] = zrow[e[j].x];        // e.x = src*8 (uint4 row offset)
#pragma unroll
        for (int j = 0; j < SBATCH; j++) {
            float w = __int_as_float(e[j].y);
            wsum += w;
            ull wk = pack2(w, w);
            float2 z0 = __half22float2(*reinterpret_cast<__half2*>(&zv[j].x));
            float2 z1 = __half22float2(*reinterpret_cast<__half2*>(&zv[j].y));
            float2 z2 = __half22float2(*reinterpret_cast<__half2*>(&zv[j].z));
            float2 z3 = __half22float2(*reinterpret_cast<__half2*>(&zv[j].w));
            ffma2(acc0, wk, pack2(z0.x, z0.y));
            ffma2(acc1, wk, pack2(z1.x, z1.y));
            ffma2(acc2, wk, pack2(z2.x, z2.y));
            ffma2(acc3, wk, pack2(z3.x, z3.y));
        }
    }

    float inv = (cnt > 0) ? 1.f / wsum : 0.f;
    if (valid) {
        float2 a = unpack2(acc0), b = unpack2(acc1);
        float2 c = unpack2(acc2), d = unpack2(acc3);
        float4* out = reinterpret_cast<float4*>(h + (size_t)node * OUT_DIM);
        out[ln * 2]     = make_float4(a.x * inv, a.y * inv, b.x * inv, b.y * inv);
        out[ln * 2 + 1] = make_float4(c.x * inv, c.y * inv, d.x * inv, d.y * inv);
        if (ln == 0) g_cnt[node] = 0;    // restore invariant for next replay
    }
}

// ---------------- launch ------------------------------------------------------
extern "C" void kernel_launch(void* const* d_in, const int* in_sizes, int n_in,
                              void* d_out, int out_size) {
    const float* feat = (const float*)d_in[0];
    const int*   src  = (const int*)  d_in[1];
    const int*   dst  = (const int*)  d_in[2];
    const float* W    = (const float*)d_in[3];
    const float* a    = (const float*)d_in[4];
    float* h = (float*)d_out;

    int n_nodes = in_sizes[0] / IN_DIM;
    int n_edges = in_sizes[1];

    proj_kernel<<<(n_nodes + 63) / 64, 128>>>(feat, W, a, n_nodes);

    fill_kernel<<<(n_edges / 4 + 255) / 256, 256>>>(src, dst, n_edges);

    {
        int warps = (n_nodes + 3) / 4;
        int blocks = (warps + 7) / 8;    // 8 warps/block
        scatter_kernel<<<blocks, 256>>>(h, n_nodes);
    }
}

// round 16
// speedup vs baseline: 1.2863x; 1.0563x over previous
#include <cuda_runtime.h>
#include <cuda_fp16.h>
#include <cstdint>

#define MAX_NODES 50048
#define IN_DIM    128
#define OUT_DIM   64
#define LEAKY     0.01f
#define CAP       128           // slots per destination node (max degree ~35)

typedef unsigned long long ull;

// ---------------- scratch (device globals; zero-initialized at load) -------
__device__ uint2 g_zu[MAX_NODES * 16];        // projected features fp16; row=128B
__device__ float g_azs[MAX_NODES];            // z . a[:64]  (fp32 precision)
__device__ float g_azd[MAX_NODES];            // z . a[64:]
__device__ int   g_cnt[MAX_NODES];            // per-dst cursor/degree (re-zeroed by scatter)
__device__ int2  g_sw[MAX_NODES * CAP];       // slotted CSR: (src*8, exp(e) bits)

// ---------------- packed f32x2 helpers --------------------------------------
__device__ __forceinline__ ull pack2(float lo, float hi) {
    ull r;
    asm("mov.b64 %0, {%1, %2};" : "=l"(r) : "f"(lo), "f"(hi));
    return r;
}
__device__ __forceinline__ void ffma2(ull& d, ull a, ull b) {
    asm("fma.rn.f32x2 %0, %1, %2, %0;" : "+l"(d) : "l"(a), "l"(b));
}
__device__ __forceinline__ float2 unpack2(ull v) {
    float lo, hi;
    asm("mov.b64 {%0, %1}, %2;" : "=f"(lo), "=f"(hi) : "l"(v));
    return make_float2(lo, hi);
}

// ---------------- kernel 1: smem-staged, double-buffered projection ---------
// 256 threads, 128 nodes/block. jg=tid&15 owns 2 column pairs; g=tid>>4 owns
// 8 nodes. F streamed in 8 chunks (16 k each) through a padded smem tile with
// coalesced LDG.128 prefetched a full chunk ahead (DRAM latency hidden).
#define FS_ELEMS 528   // 128 nodes * 4 float4 + 16 pad (one per 8 nodes)
__global__ void __launch_bounds__(256)
proj_kernel(const float* __restrict__ feat,
            const float* __restrict__ W,
            const float* __restrict__ a,
            int n_nodes) {
    int tid = threadIdx.x;

    __shared__ ull    Ws2[IN_DIM * 32];   // [k][pair], 32 KB
    __shared__ float4 Fs[2][FS_ELEMS];    // 16.9 KB double-buffered F tile
    __shared__ float  as[2 * OUT_DIM];

    const float4* W4 = reinterpret_cast<const float4*>(W);
    for (int i = tid; i < IN_DIM * OUT_DIM / 4; i += 256) {
        float4 w = W4[i];
        Ws2[2 * i]     = pack2(w.x, w.y);
        Ws2[2 * i + 1] = pack2(w.z, w.w);
    }
    if (tid < 2 * OUT_DIM) as[tid] = a[tid];

    int jg = tid & 15;           // pair group: pairs jg*2, jg*2+1
    int g  = tid >> 4;           // node group: nodes g*8 .. g*8+7 (local)
    int nb = blockIdx.x * 128;
    if (nb > n_nodes - 128) nb = n_nodes - 128;   // tail: duplicate work, same values

    const float4* F4 = reinterpret_cast<const float4*>(feat) + (size_t)nb * 32;

    // loader: 512 float4 per chunk, 2 per thread
    int i0 = tid,        l0 = i0 >> 2, q0 = i0 & 3;
    int i1 = tid + 256,  l1 = i1 >> 2, q1 = i1 & 3;
    int o0 = l0 * 4 + q0 + (l0 >> 3);
    int o1 = l1 * 4 + q1 + (l1 >> 3);

    // preload chunk 0
    float4 r0 = F4[(size_t)l0 * 32 + q0];
    float4 r1 = F4[(size_t)l1 * 32 + q1];
    Fs[0][o0] = r0;
    Fs[0][o1] = r1;
    __syncthreads();

    ull acc[8][2];
#pragma unroll
    for (int i = 0; i < 8; i++) { acc[i][0] = 0ull; acc[i][1] = 0ull; }

    for (int c = 0; c < 8; c++) {
        int buf = c & 1;
        if (c < 7) {   // prefetch next chunk (consumed ~1500 cyc later)
            r0 = F4[(size_t)l0 * 32 + (c + 1) * 4 + q0];
            r1 = F4[(size_t)l1 * 32 + (c + 1) * 4 + q1];
        }
        int kbase = c * 16;
#pragma unroll
        for (int q = 0; q < 4; q++) {
            ull wp[8];
#pragma unroll
            for (int ks = 0; ks < 4; ks++) {
                int k = kbase + q * 4 + ks;
                wp[2 * ks]     = Ws2[k * 32 + jg * 2];
                wp[2 * ks + 1] = Ws2[k * 32 + jg * 2 + 1];
            }
#pragma unroll
            for (int i = 0; i < 8; i++) {
                float4 f = Fs[buf][(g * 8 + i) * 4 + q + g];   // padded, conflict-free
                ull fx = pack2(f.x, f.x);
                ffma2(acc[i][0], fx, wp[0]);
                ffma2(acc[i][1], fx, wp[1]);
                ull fy = pack2(f.y, f.y);
                ffma2(acc[i][0], fy, wp[2]);
                ffma2(acc[i][1], fy, wp[3]);
                ull fz = pack2(f.z, f.z);
                ffma2(acc[i][0], fz, wp[4]);
                ffma2(acc[i][1], fz, wp[5]);
                ull fw = pack2(f.w, f.w);
                ffma2(acc[i][0], fw, wp[6]);
                ffma2(acc[i][1], fw, wp[7]);
            }
        }
        if (c < 7) {
            Fs[buf ^ 1][o0] = r0;
            Fs[buf ^ 1][o1] = r1;
        }
        __syncthreads();
    }

    // az partials per node, reduced across the 16 jg lanes
    int n0 = nb + g * 8;
#pragma unroll
    for (int i = 0; i < 8; i++) {
        float2 v0 = unpack2(acc[i][0]);
        float2 v1 = unpack2(acc[i][1]);
        int c0 = jg * 4;
        float s0 = v0.x * as[c0]     + v0.y * as[c0 + 1]
                 + v1.x * as[c0 + 2] + v1.y * as[c0 + 3];
        float s1 = v0.x * as[OUT_DIM + c0]     + v0.y * as[OUT_DIM + c0 + 1]
                 + v1.x * as[OUT_DIM + c0 + 2] + v1.y * as[OUT_DIM + c0 + 3];
        s0 += __shfl_xor_sync(0xffffffffu, s0, 1);
        s0 += __shfl_xor_sync(0xffffffffu, s0, 2);
        s0 += __shfl_xor_sync(0xffffffffu, s0, 4);
        s0 += __shfl_xor_sync(0xffffffffu, s0, 8);
        s1 += __shfl_xor_sync(0xffffffffu, s1, 1);
        s1 += __shfl_xor_sync(0xffffffffu, s1, 2);
        s1 += __shfl_xor_sync(0xffffffffu, s1, 4);
        s1 += __shfl_xor_sync(0xffffffffu, s1, 8);
        if (jg == 0) {
            g_azs[n0 + i] = s0;
            g_azd[n0 + i] = s1;
        }
    }

    // z stores: fp16; 2 half2 = 8B = 1 uint2 per node per thread
#pragma unroll
    for (int i = 0; i < 8; i++) {
        __half2 h0 = __float22half2_rn(unpack2(acc[i][0]));
        __half2 h1 = __float22half2_rn(unpack2(acc[i][1]));
        uint2 v;
        v.x = *reinterpret_cast<unsigned*>(&h0);
        v.y = *reinterpret_cast<unsigned*>(&h1);
        g_zu[(size_t)(n0 + i) * 16 + jg] = v;
    }
}

// ---------------- kernel 2: edge weights + slotted CSR fill ------------------
// No scan needed: slot = atomicAdd(cursor). 4 edges/thread via int4 loads.
__global__ void __launch_bounds__(256)
fill_kernel(const int* __restrict__ src,
            const int* __restrict__ dst,
            int n_edges) {
    int t = blockIdx.x * 256 + threadIdx.x;
    int e0 = t * 4;
    if (e0 >= n_edges) return;

    if (e0 + 3 < n_edges) {
        int4 s4 = *reinterpret_cast<const int4*>(src + e0);
        int4 d4 = *reinterpret_cast<const int4*>(dst + e0);
        float ea = g_azs[s4.x] + g_azd[d4.x];
        float eb = g_azs[s4.y] + g_azd[d4.y];
        float ec = g_azs[s4.z] + g_azd[d4.z];
        float ed = g_azs[s4.w] + g_azd[d4.w];
        ea = (ea > 0.f) ? ea : LEAKY * ea;
        eb = (eb > 0.f) ? eb : LEAKY * eb;
        ec = (ec > 0.f) ? ec : LEAKY * ec;
        ed = (ed > 0.f) ? ed : LEAKY * ed;
        float wa = __expf(ea), wb = __expf(eb);
        float wc = __expf(ec), wd = __expf(ed);
        int pa = atomicAdd(&g_cnt[d4.x], 1);
        int pb = atomicAdd(&g_cnt[d4.y], 1);
        int pc = atomicAdd(&g_cnt[d4.z], 1);
        int pd = atomicAdd(&g_cnt[d4.w], 1);
        if (pa < CAP) g_sw[(size_t)d4.x * CAP + pa] = make_int2(s4.x << 3, __float_as_int(wa));
        if (pb < CAP) g_sw[(size_t)d4.y * CAP + pb] = make_int2(s4.y << 3, __float_as_int(wb));
        if (pc < CAP) g_sw[(size_t)d4.z * CAP + pc] = make_int2(s4.z << 3, __float_as_int(wc));
        if (pd < CAP) g_sw[(size_t)d4.w * CAP + pd] = make_int2(s4.w << 3, __float_as_int(wd));
    } else {
        for (int e = e0; e < n_edges; e++) {
            int s = src[e], d = dst[e];
            float ee = g_azs[s] + g_azd[d];
            ee = (ee > 0.f) ? ee : LEAKY * ee;
            float w = __expf(ee);
            int pos = atomicAdd(&g_cnt[d], 1);
            if (pos < CAP) g_sw[(size_t)d * CAP + pos] = make_int2(s << 3, __float_as_int(w));
        }
    }
}

// ---------------- kernel 3: four destination nodes per warp ------------------
// Quarter-warp (8 lanes) owns one node; lane owns uint4 = 8 fp16 cols (16B);
// full 128B row in one LDG.128 per edge. SBATCH=4; fp32 accumulation.
#define SBATCH 4
__global__ void __launch_bounds__(256)
scatter_kernel(float* __restrict__ h, int n_nodes) {
    int warp_id = (blockIdx.x * 256 + threadIdx.x) >> 5;
    int lane = threadIdx.x & 31;
    int qw = lane >> 3;          // quarter-warp id: 0..3
    int ln = lane & 7;           // uint4 index within row

    int node = warp_id * 4 + qw;
    bool valid = node < n_nodes;

    int cnt = valid ? g_cnt[node] : 0;
    cnt = (cnt < CAP) ? cnt : CAP;          // memory-safety guard (never binds)

    const uint4* zrow = reinterpret_cast<const uint4*>(g_zu) + ln;
    const int2* sw = g_sw + (size_t)(valid ? node : 0) * CAP;

    ull acc0 = 0ull, acc1 = 0ull, acc2 = 0ull, acc3 = 0ull;
    float wsum = 0.f;

    for (int base = 0; base < cnt; base += SBATCH) {
        int m = cnt - base;
        int2 e[SBATCH];
#pragma unroll
        for (int j = 0; j < SBATCH; j++)
            e[j] = (j < m) ? __ldg(sw + base + j) : make_int2(0, 0);
        uint4 zv[SBATCH];
#pragma unroll
        for (int j = 0; j < SBATCH; j++)
            zv[j] = zrow[e[j].x];        // e.x = src*8 (uint4 row offset)
#pragma unroll
        for (int j = 0; j < SBATCH; j++) {
            float w = __int_as_float(e[j].y);
            wsum += w;
            ull wk = pack2(w, w);
            float2 z0 = __half22float2(*reinterpret_cast<__half2*>(&zv[j].x));
            float2 z1 = __half22float2(*reinterpret_cast<__half2*>(&zv[j].y));
            float2 z2 = __half22float2(*reinterpret_cast<__half2*>(&zv[j].z));
            float2 z3 = __half22float2(*reinterpret_cast<__half2*>(&zv[j].w));
            ffma2(acc0, wk, pack2(z0.x, z0.y));
            ffma2(acc1, wk, pack2(z1.x, z1.y));
            ffma2(acc2, wk, pack2(z2.x, z2.y));
            ffma2(acc3, wk, pack2(z3.x, z3.y));
        }
    }

    float inv = (cnt > 0) ? 1.f / wsum : 0.f;
    if (valid) {
        float2 a = unpack2(acc0), b = unpack2(acc1);
        float2 c = unpack2(acc2), d = unpack2(acc3);
        float4* out = reinterpret_cast<float4*>(h + (size_t)node * OUT_DIM);
        out[ln * 2]     = make_float4(a.x * inv, a.y * inv, b.x * inv, b.y * inv);
        out[ln * 2 + 1] = make_float4(c.x * inv, c.y * inv, d.x * inv, d.y * inv);
        if (ln == 0) g_cnt[node] = 0;    // restore invariant for next replay
    }
}

// ---------------- launch ------------------------------------------------------
extern "C" void kernel_launch(void* const* d_in, const int* in_sizes, int n_in,
                              void* d_out, int out_size) {
    const float* feat = (const float*)d_in[0];
    const int*   src  = (const int*)  d_in[1];
    const int*   dst  = (const int*)  d_in[2];
    const float* W    = (const float*)d_in[3];
    const float* a    = (const float*)d_in[4];
    float* h = (float*)d_out;

    int n_nodes = in_sizes[0] / IN_DIM;
    int n_edges = in_sizes[1];

    proj_kernel<<<(n_nodes + 127) / 128, 256>>>(feat, W, a, n_nodes);

    fill_kernel<<<(n_edges / 4 + 255) / 256, 256>>>(src, dst, n_edges);

    {
        int warps = (n_nodes + 3) / 4;
        int blocks = (warps + 7) / 8;    // 8 warps/block
        scatter_kernel<<<blocks, 256>>>(h, n_nodes);
    }
}